// round 5
// baseline (speedup 1.0000x reference)
#include <cuda_runtime.h>
#include <cuda_bf16.h>
#include <cstdint>

#define DINLINE __device__ __forceinline__

namespace {
constexpr int CIN = 512, PIX = 3136, NWIN = 8, WSTRIDE = 32;
constexpr int TM = 128;      // pixels per tile (MMA M)
constexpr int TPC = 5;       // tiles per CTA
constexpr int NBLK = 5;      // grid.x ; NBLK*TPC = 25 tiles, last is partial
}

// W fragments, register-order: idx = term*2048 + ng*1024 + ks*256 + j*64 + r*32 + lane
// value = bf16x2{ lo = W[n][k], hi = W[n][k+1] },  n = ng*32 + j*8 + (lane>>2),
// k = ks*16 + r*8 + (lane&3)*2.   term0 = hi-split, term1 = lo-split (residual).
__device__ __align__(16) uint32_t g_wB[4096];

// pack {upper16 = bf16(a_hi), lower16 = bf16(a_lo)}
DINLINE uint32_t cvt2(float a_hi, float a_lo) {
    uint32_t r;
    asm("cvt.rn.bf16x2.f32 %0, %1, %2;" : "=r"(r) : "f"(a_hi), "f"(a_lo));
    return r;
}

__global__ void prep_w(const float* __restrict__ w) {
    int t = threadIdx.x;
#pragma unroll
    for (int i = 0; i < 16; i++) {
        int idx  = i * 256 + t;
        int lane = idx & 31;
        int r    = (idx >> 5) & 1;
        int j    = (idx >> 6) & 3;
        int ks   = (idx >> 8) & 3;
        int ng   = (idx >> 10) & 1;
        int term = (idx >> 11) & 1;
        int n = ng * 32 + j * 8 + (lane >> 2);
        int k = ks * 16 + r * 8 + (lane & 3) * 2;
        float v0 = w[n * 64 + k], v1 = w[n * 64 + k + 1];
        uint32_t hp = cvt2(v1, v0);
        uint32_t val;
        if (term == 0) {
            val = hp;
        } else {
            float h0 = __uint_as_float(hp << 16);
            float h1 = __uint_as_float(hp & 0xFFFF0000u);
            val = cvt2(v1 - h1, v0 - h0);
        }
        g_wB[idx] = val;
    }
}

// ---- PTX helpers ----
DINLINE uint32_t smem_u32(const void* p) {
    uint32_t a;
    asm("{ .reg .u64 t; cvta.to.shared.u64 t, %1; cvt.u32.u64 %0, t; }" : "=r"(a) : "l"(p));
    return a;
}
DINLINE void ldsm4(uint32_t* r, uint32_t a) {
    asm volatile("ldmatrix.sync.aligned.m8n8.x4.shared.b16 {%0,%1,%2,%3}, [%4];"
                 : "=r"(r[0]), "=r"(r[1]), "=r"(r[2]), "=r"(r[3]) : "r"(a));
}
DINLINE void mma_bf16(float* c, const uint32_t* a, uint32_t b0, uint32_t b1) {
    asm volatile(
        "mma.sync.aligned.m16n8k16.row.col.f32.bf16.bf16.f32 "
        "{%0,%1,%2,%3}, {%4,%5,%6,%7}, {%8,%9}, {%0,%1,%2,%3};"
        : "+f"(c[0]), "+f"(c[1]), "+f"(c[2]), "+f"(c[3])
        : "r"(a[0]), "r"(a[1]), "r"(a[2]), "r"(a[3]), "r"(b0), "r"(b1));
}

__global__ void __launch_bounds__(256, 2)
win_mma(const float* __restrict__ x, float* __restrict__ out) {
    // x tile staging only: hi at 0, lo at 16384. [128 px rows x 128B], row-swizzled.
    __shared__ __align__(16) char smem[32768];
    const uint32_t sb = smem_u32(smem);
    const int t = threadIdx.x;
    const int lane = t & 31, w = t >> 5;
    const int mg = w & 3, ng = w >> 2;    // warp = (4 M-groups) x (2 N-groups)
    const int nwin = blockIdx.y, b = blockIdx.z;
    const int tile0 = blockIdx.x * TPC;

    // ---- load all B fragments into registers (once per CTA) ----
    uint32_t bh[4][4][2], bl[4][4][2];    // [ks][j][r]
    {
        const uint32_t* ph = g_wB + ng * 1024 + lane;
        const uint32_t* pl_ = g_wB + 2048 + ng * 1024 + lane;
#pragma unroll
        for (int ks = 0; ks < 4; ks++)
#pragma unroll
            for (int j = 0; j < 4; j++)
#pragma unroll
                for (int r = 0; r < 2; r++) {
                    int off = ks * 256 + j * 64 + r * 32;
                    bh[ks][j][r] = ph[off];
                    bl[ks][j][r] = pl_[off];
                }
    }

    // A staging constants
    const int pl = t & 127;               // pixel row this thread stages
    const int kh = (t >> 7) * 32;         // k half
    // A ldmatrix lane address pieces
    const int rA0 = mg * 32 + ((lane >> 3) & 1) * 8 + (lane & 7);
    const int cA = (lane >> 4) * 16;
    // epilogue pieces
    const int grp = lane >> 2, tid4 = lane & 3;
    float* ob = out + ((size_t)(b * CIN + nwin)) * PIX;

    for (int it = 0; it < TPC; it++) {
        const int tile = tile0 + it;

        // ---- stage x tile: [64 k][128 px] -> bf16 hi/lo [px][k] swizzled ----
        if (it > 0) __syncthreads();      // previous iter's ldsm reads done
        {
            int p = tile * TM + pl;
            if (p >= PIX) p = PIX - 1;    // tail clamp; writes guarded later
            const float* xp = x + ((size_t)(b * CIN + nwin * WSTRIDE + kh)) * PIX + p;
#pragma unroll
            for (int c = 0; c < 4; c++) {
                float v[8];
#pragma unroll
                for (int j = 0; j < 8; j++) v[j] = xp[(size_t)(c * 8 + j) * PIX];
                uint32_t h[4], l[4];
#pragma unroll
                for (int j = 0; j < 4; j++) {
                    uint32_t hp = cvt2(v[2 * j + 1], v[2 * j]);
                    float he = __uint_as_float(hp << 16);
                    float ho = __uint_as_float(hp & 0xFFFF0000u);
                    h[j] = hp;
                    l[j] = cvt2(v[2 * j + 1] - ho, v[2 * j] - he);
                }
                uint32_t off = (uint32_t)(pl * 128 + ((kh * 2 + c * 16) ^ ((pl & 7) << 4)));
                *(uint4*)(smem + off) = make_uint4(h[0], h[1], h[2], h[3]);
                *(uint4*)(smem + 16384 + off) = make_uint4(l[0], l[1], l[2], l[3]);
            }
        }
        __syncthreads();

        // ---- MMA: warp computes M32 (rows mg*32..+31) x N32 (cols ng*32..+31) ----
        float acc[2][4][4];
#pragma unroll
        for (int mf = 0; mf < 2; mf++)
#pragma unroll
            for (int j = 0; j < 4; j++)
#pragma unroll
                for (int i = 0; i < 4; i++) acc[mf][j][i] = 0.0f;

#pragma unroll
        for (int ks = 0; ks < 4; ks++) {
#pragma unroll
            for (int mf = 0; mf < 2; mf++) {
                const int row = rA0 + mf * 16;
                uint32_t ca = (uint32_t)((ks * 32 + cA) ^ ((row & 7) << 4));
                uint32_t addr = sb + row * 128 + ca;
                uint32_t ah[4], al[4];
                ldsm4(ah, addr);
                ldsm4(al, addr + 16384);
#pragma unroll
                for (int j = 0; j < 4; j++) {
                    mma_bf16(acc[mf][j], ah, bh[ks][j][0], bh[ks][j][1]);
                    mma_bf16(acc[mf][j], al, bh[ks][j][0], bh[ks][j][1]);
                    mma_bf16(acc[mf][j], ah, bl[ks][j][0], bl[ks][j][1]);
                }
            }
        }

        // ---- epilogue: direct STG ----
#pragma unroll
        for (int mf = 0; mf < 2; mf++) {
            const int px0 = tile * TM + mg * 32 + mf * 16 + grp;
            const bool v0 = px0 < PIX, v1 = (px0 + 8) < PIX;
#pragma unroll
            for (int j = 0; j < 4; j++) {
                int o = ng * 32 + j * 8 + tid4 * 2;
                size_t s0 = (size_t)(o * NWIN) * PIX;
                size_t s1 = (size_t)((o + 1) * NWIN) * PIX;
                if (v0) { ob[s0 + px0] = acc[mf][j][0]; ob[s1 + px0] = acc[mf][j][1]; }
                if (v1) { ob[s0 + px0 + 8] = acc[mf][j][2]; ob[s1 + px0 + 8] = acc[mf][j][3]; }
            }
        }
    }
}

extern "C" void kernel_launch(void* const* d_in, const int* in_sizes, int n_in,
                              void* d_out, int out_size) {
    const float* x = (const float*)d_in[0];   // (32, 512, 56, 56) fp32
    const float* w = (const float*)d_in[1];   // (64, 64) fp32
    float* out = (float*)d_out;               // (32, 512, 56, 56) fp32

    prep_w<<<1, 256>>>(w);
    dim3 grid(NBLK, NWIN, 32);
    win_mma<<<grid, 256>>>(x, out);
}

// round 6
// speedup vs baseline: 1.2779x; 1.2779x over previous
#include <cuda_runtime.h>
#include <cstdint>

#define DINLINE __device__ __forceinline__

namespace {
constexpr int CIN = 512, PIX = 3136, NWIN = 8, WSTRIDE = 32;
constexpr int TM = 64;            // pixels per tile; 3136 = 49*64 exactly (no tail)
constexpr int TPC = 7, NBLK = 7;  // 49 tiles = 7 blocks x 7 tiles
constexpr int ROWF = 72;          // padded row stride in floats (bank-conflict-free)
constexpr int ROWB = ROWF * 4;    // 288 B
constexpr int BUFB = 64 * ROWB;   // 18432 B per buffer
}

// W fragments (tf32-rounded fp32 bits), register order:
// idx = ng*2048 + ((ks*4 + j)*2 + r)*32 + lane
// n = ng*32 + j*8 + (lane>>2), k = ks*8 + (lane&3) + r*4
__device__ __align__(16) uint32_t g_wB[4096];

DINLINE uint32_t f2tf32(float f) {
    uint32_t r;
    asm("cvt.rna.tf32.f32 %0, %1;" : "=r"(r) : "f"(f));
    return r;
}

__global__ void prep_w(const float* __restrict__ w) {
    int t = threadIdx.x;
#pragma unroll
    for (int i = 0; i < 16; i++) {
        int idx  = i * 256 + t;
        int lane = idx & 31;
        int r    = (idx >> 5) & 1;
        int j    = (idx >> 6) & 3;
        int ks   = (idx >> 8) & 7;
        int ng   = (idx >> 11) & 1;
        int n = ng * 32 + j * 8 + (lane >> 2);
        int k = ks * 8 + (lane & 3) + r * 4;
        g_wB[idx] = f2tf32(w[n * 64 + k]);
    }
}

// ---- PTX helpers ----
DINLINE uint32_t smem_u32(const void* p) {
    uint32_t a;
    asm("{ .reg .u64 t; cvta.to.shared.u64 t, %1; cvt.u32.u64 %0, t; }" : "=r"(a) : "l"(p));
    return a;
}
DINLINE void cp16(uint32_t dst, const void* src) {
    asm volatile("cp.async.cg.shared.global [%0], [%1], 16;" :: "r"(dst), "l"(src) : "memory");
}
DINLINE float lds32(uint32_t a) {
    float f;
    asm volatile("ld.shared.f32 %0, [%1];" : "=f"(f) : "r"(a));
    return f;
}
DINLINE void mma_tf32(float* c, uint32_t a0, uint32_t a1, uint32_t a2, uint32_t a3,
                      uint32_t b0, uint32_t b1) {
    asm volatile(
        "mma.sync.aligned.m16n8k8.row.col.f32.tf32.tf32.f32 "
        "{%0,%1,%2,%3}, {%4,%5,%6,%7}, {%8,%9}, {%0,%1,%2,%3};"
        : "+f"(c[0]), "+f"(c[1]), "+f"(c[2]), "+f"(c[3])
        : "r"(a0), "r"(a1), "r"(a2), "r"(a3), "r"(b0), "r"(b1));
}

__global__ void __launch_bounds__(256, 2)
win_mma(const float* __restrict__ x, float* __restrict__ out) {
    __shared__ __align__(16) char smem[2 * BUFB];
    const uint32_t sb = smem_u32(smem);
    const int t = threadIdx.x;
    const int lane = t & 31, w = t >> 5;
    const int mg = w & 3, ng = w >> 2;     // 4 M16-groups x 2 N32-groups
    const int nwin = blockIdx.y, b = blockIdx.z;
    const int tile0 = blockIdx.x * TPC;

    // ---- B fragments: K=64, N=32 per warp, tf32, loaded once per CTA ----
    uint32_t bw[8][4][2];
    {
        const uint32_t* base = g_wB + ng * 2048 + lane;
#pragma unroll
        for (int ks = 0; ks < 8; ks++)
#pragma unroll
            for (int j = 0; j < 4; j++)
#pragma unroll
                for (int r = 0; r < 2; r++)
                    bw[ks][j][r] = base[((ks * 4 + j) * 2 + r) * 32];
    }

    // staging: 1024 chunks of 16B per tile, 4 per thread
    const float* xb = x + ((size_t)(b * CIN + nwin * WSTRIDE)) * PIX;
    const int sk = t >> 4;          // base row pair: q=i*256+t -> k=(q>>4)
    const int sc = t & 15;          // chunk col
    // A-fragment lane pieces
    const int pA = mg * 16 + (lane >> 2);
    const int kA = lane & 3;
    // epilogue pieces
    const int grp = lane >> 2, tid4 = lane & 3;
    float* ob = out + ((size_t)(b * CIN + nwin)) * PIX;

    // ---- prologue: stage tile0 into buffer 0 ----
    {
        const float* src = xb + (size_t)sk * PIX + tile0 * TM + sc * 4;
        uint32_t dst = sb + sk * ROWB + sc * 16;
#pragma unroll
        for (int i = 0; i < 4; i++)
            cp16(dst + i * 16 * ROWB, src + (size_t)(i * 16) * PIX);
        asm volatile("cp.async.commit_group;" ::: "memory");
    }

    for (int it = 0; it < TPC; it++) {
        // stage next tile into the other buffer
        if (it + 1 < TPC) {
            const float* src = xb + (size_t)sk * PIX + (tile0 + it + 1) * TM + sc * 4;
            uint32_t dst = sb + ((it + 1) & 1) * BUFB + sk * ROWB + sc * 16;
#pragma unroll
            for (int i = 0; i < 4; i++)
                cp16(dst + i * 16 * ROWB, src + (size_t)(i * 16) * PIX);
            asm volatile("cp.async.commit_group;" ::: "memory");
            asm volatile("cp.async.wait_group 1;" ::: "memory");
        } else {
            asm volatile("cp.async.wait_group 0;" ::: "memory");
        }
        __syncthreads();   // staged data visible to all warps

        // ---- MMA: warp tile M16 (rows mg*16..+15) x N32 (cols ng*32..+31) ----
        float acc[4][4];
#pragma unroll
        for (int j = 0; j < 4; j++)
#pragma unroll
            for (int i = 0; i < 4; i++) acc[j][i] = 0.0f;

        const uint32_t bufb = sb + (it & 1) * BUFB;
#pragma unroll
        for (int ks = 0; ks < 8; ks++) {
            // A fragment from raw [k][px] fp32 buffer (conflict-free LDS.32)
            uint32_t a0a = bufb + (uint32_t)((ks * 8 + kA) * ROWB + pA * 4);
            uint32_t a0 = f2tf32(lds32(a0a));
            uint32_t a1 = f2tf32(lds32(a0a + 32));            // row +8 px
            uint32_t a2 = f2tf32(lds32(a0a + 4 * ROWB));      // k +4
            uint32_t a3 = f2tf32(lds32(a0a + 4 * ROWB + 32));
#pragma unroll
            for (int j = 0; j < 4; j++)
                mma_tf32(acc[j], a0, a1, a2, a3, bw[ks][j][0], bw[ks][j][1]);
        }

        // ---- epilogue: direct STG ----
        {
            const int px0 = (tile0 + it) * TM + mg * 16 + grp;
#pragma unroll
            for (int j = 0; j < 4; j++) {
                int o = ng * 32 + j * 8 + tid4 * 2;
                size_t s0 = (size_t)(o * NWIN) * PIX;
                size_t s1 = s0 + (size_t)NWIN * PIX;
                ob[s0 + px0] = acc[j][0];
                ob[s1 + px0] = acc[j][1];
                ob[s0 + px0 + 8] = acc[j][2];
                ob[s1 + px0 + 8] = acc[j][3];
            }
        }
        __syncthreads();   // all reads of buf[it&1] done before it's restaged
    }
}

extern "C" void kernel_launch(void* const* d_in, const int* in_sizes, int n_in,
                              void* d_out, int out_size) {
    const float* x = (const float*)d_in[0];   // (32, 512, 56, 56) fp32
    const float* w = (const float*)d_in[1];   // (64, 64) fp32
    float* out = (float*)d_out;               // (32, 512, 56, 56) fp32

    prep_w<<<1, 256>>>(w);
    dim3 grid(NBLK, NWIN, 32);
    win_mma<<<grid, 256>>>(x, out);
}

// round 7
// speedup vs baseline: 1.3203x; 1.0332x over previous
#include <cuda_runtime.h>
#include <cstdint>

#define DINLINE __device__ __forceinline__

namespace {
constexpr int CIN = 512, PIX = 3136, NWIN = 8, WSTRIDE = 32;
constexpr int TM = 128;           // pixels per tile; 25 tiles, last has 64 valid px
constexpr int TPC = 5, NBLK = 5;  // 25 tiles = 5 blocks x 5 tiles
constexpr int ROWF = 136;         // padded row stride in floats (bank-conflict-free)
constexpr int ROWB = ROWF * 4;    // 544 B
constexpr int BUFB = 64 * ROWB;   // 34816 B per buffer
constexpr int SMEM_TOTAL = 2 * BUFB;  // 69632 B (dynamic)
}

// W fragments (tf32-rounded fp32 bits), register order:
// idx = ng*2048 + ((ks*4 + j)*2 + r)*32 + lane
// n = ng*32 + j*8 + (lane>>2), k = ks*8 + (lane&3) + r*4
__device__ __align__(16) uint32_t g_wB[4096];

DINLINE uint32_t f2tf32(float f) {
    uint32_t r;
    asm("cvt.rna.tf32.f32 %0, %1;" : "=r"(r) : "f"(f));
    return r;
}

__global__ void prep_w(const float* __restrict__ w) {
    int t = threadIdx.x;
#pragma unroll
    for (int i = 0; i < 16; i++) {
        int idx  = i * 256 + t;
        int lane = idx & 31;
        int r    = (idx >> 5) & 1;
        int j    = (idx >> 6) & 3;
        int ks   = (idx >> 8) & 7;
        int ng   = (idx >> 11) & 1;
        int n = ng * 32 + j * 8 + (lane >> 2);
        int k = ks * 8 + (lane & 3) + r * 4;
        g_wB[idx] = f2tf32(w[n * 64 + k]);
    }
}

// ---- PTX helpers ----
DINLINE uint32_t smem_u32(const void* p) {
    uint32_t a;
    asm("{ .reg .u64 t; cvta.to.shared.u64 t, %1; cvt.u32.u64 %0, t; }" : "=r"(a) : "l"(p));
    return a;
}
DINLINE void cp16(uint32_t dst, const void* src) {
    asm volatile("cp.async.cg.shared.global [%0], [%1], 16;" :: "r"(dst), "l"(src) : "memory");
}
DINLINE float lds32(uint32_t a) {
    float f;
    asm volatile("ld.shared.f32 %0, [%1];" : "=f"(f) : "r"(a));
    return f;
}
DINLINE void mma_tf32(float* c, uint32_t a0, uint32_t a1, uint32_t a2, uint32_t a3,
                      uint32_t b0, uint32_t b1) {
    asm volatile(
        "mma.sync.aligned.m16n8k8.row.col.f32.tf32.tf32.f32 "
        "{%0,%1,%2,%3}, {%4,%5,%6,%7}, {%8,%9}, {%0,%1,%2,%3};"
        : "+f"(c[0]), "+f"(c[1]), "+f"(c[2]), "+f"(c[3])
        : "r"(a0), "r"(a1), "r"(a2), "r"(a3), "r"(b0), "r"(b1));
}

__global__ void __launch_bounds__(256, 2)
win_mma(const float* __restrict__ x, float* __restrict__ out) {
    extern __shared__ __align__(16) char smem[];
    const uint32_t sb = smem_u32(smem);
    const int t = threadIdx.x;
    const int lane = t & 31, w = t >> 5;
    const int mg = w & 3, ng = w >> 2;     // 4 M32-groups x 2 N32-groups
    const int nwin = blockIdx.y, b = blockIdx.z;
    const int tile0 = blockIdx.x * TPC;

    // ---- B fragments: K=64, N=32 per warp, tf32, loaded once per CTA ----
    uint32_t bw[8][4][2];
    {
        const uint32_t* base = g_wB + ng * 2048 + lane;
#pragma unroll
        for (int ks = 0; ks < 8; ks++)
#pragma unroll
            for (int j = 0; j < 4; j++)
#pragma unroll
                for (int r = 0; r < 2; r++)
                    bw[ks][j][r] = base[((ks * 4 + j) * 2 + r) * 32];
    }

    // staging: 2048 chunks of 16B per tile, 8 per thread; q = i*256+t
    const float* xb = x + ((size_t)(b * CIN + nwin * WSTRIDE)) * PIX;
    const int sk = t >> 5;          // row for i=0; rows step by 8 per i
    const int sc = t & 31;          // chunk col (32 per 128-px row)
    // A-fragment lane pieces
    const int pA = lane >> 2;       // px within 16-row group
    const int kA = lane & 3;
    // epilogue pieces
    const int grp = lane >> 2, tid4 = lane & 3;
    float* ob = out + ((size_t)(b * CIN + nwin)) * PIX;

    // ---- prologue: stage tile0 into buffer 0 ----
    {
        const float* src = xb + (size_t)sk * PIX + tile0 * TM + sc * 4;
        uint32_t dst = sb + sk * ROWB + sc * 16;
#pragma unroll
        for (int i = 0; i < 8; i++)
            cp16(dst + i * 8 * ROWB, src + (size_t)(i * 8) * PIX);
        asm volatile("cp.async.commit_group;" ::: "memory");
    }

    for (int it = 0; it < TPC; it++) {
        // stage next tile into the other buffer
        if (it + 1 < TPC) {
            const float* src = xb + (size_t)sk * PIX + (tile0 + it + 1) * TM + sc * 4;
            uint32_t dst = sb + ((it + 1) & 1) * BUFB + sk * ROWB + sc * 16;
#pragma unroll
            for (int i = 0; i < 8; i++)
                cp16(dst + i * 8 * ROWB, src + (size_t)(i * 8) * PIX);
            asm volatile("cp.async.commit_group;" ::: "memory");
            asm volatile("cp.async.wait_group 1;" ::: "memory");
        } else {
            asm volatile("cp.async.wait_group 0;" ::: "memory");
        }
        __syncthreads();   // staged data visible to all warps

        // ---- MMA: warp tile M32 (rows mg*32..+31) x N32 (cols ng*32..+31) ----
        float acc[2][4][4];
#pragma unroll
        for (int mf = 0; mf < 2; mf++)
#pragma unroll
            for (int j = 0; j < 4; j++)
#pragma unroll
                for (int i = 0; i < 4; i++) acc[mf][j][i] = 0.0f;

        const uint32_t bufb = sb + (it & 1) * BUFB;
#pragma unroll
        for (int ks = 0; ks < 8; ks++) {
#pragma unroll
            for (int mf = 0; mf < 2; mf++) {
                // A fragment from raw [k][px] fp32 buffer (conflict-free LDS.32)
                int px = mg * 32 + mf * 16 + pA;
                uint32_t a0a = bufb + (uint32_t)((ks * 8 + kA) * ROWB + px * 4);
                uint32_t a0 = f2tf32(lds32(a0a));
                uint32_t a1 = f2tf32(lds32(a0a + 32));            // px +8
                uint32_t a2 = f2tf32(lds32(a0a + 4 * ROWB));      // k +4
                uint32_t a3 = f2tf32(lds32(a0a + 4 * ROWB + 32));
#pragma unroll
                for (int j = 0; j < 4; j++)
                    mma_tf32(acc[mf][j], a0, a1, a2, a3, bw[ks][j][0], bw[ks][j][1]);
            }
        }

        // ---- epilogue: direct STG (guarded for the tail tile) ----
#pragma unroll
        for (int mf = 0; mf < 2; mf++) {
            const int px0 = (tile0 + it) * TM + mg * 32 + mf * 16 + grp;
            const bool v0 = px0 < PIX, v1 = (px0 + 8) < PIX;
#pragma unroll
            for (int j = 0; j < 4; j++) {
                int o = ng * 32 + j * 8 + tid4 * 2;
                size_t s0 = (size_t)(o * NWIN) * PIX;
                size_t s1 = s0 + (size_t)NWIN * PIX;
                if (v0) { ob[s0 + px0] = acc[mf][j][0]; ob[s1 + px0] = acc[mf][j][1]; }
                if (v1) { ob[s0 + px0 + 8] = acc[mf][j][2]; ob[s1 + px0 + 8] = acc[mf][j][3]; }
            }
        }
        __syncthreads();   // all reads of buf[it&1] done before restaging
    }
}

extern "C" void kernel_launch(void* const* d_in, const int* in_sizes, int n_in,
                              void* d_out, int out_size) {
    const float* x = (const float*)d_in[0];   // (32, 512, 56, 56) fp32
    const float* w = (const float*)d_in[1];   // (64, 64) fp32
    float* out = (float*)d_out;               // (32, 512, 56, 56) fp32

    cudaFuncSetAttribute(win_mma, cudaFuncAttributeMaxDynamicSharedMemorySize, SMEM_TOTAL);
    prep_w<<<1, 256>>>(w);
    dim3 grid(NBLK, NWIN, 32);
    win_mma<<<grid, 256, SMEM_TOTAL>>>(x, out);
}